// round 9
// baseline (speedup 1.0000x reference)
#include <cuda_runtime.h>
#include <cstdint>

#define NQ 4
#define NL 8

__device__ __align__(16) float g_T[112];   // 27 x (d0,d1,d2,pad)

__device__ __forceinline__ float2 cmul(float2 a, float2 b) {
    return make_float2(fmaf(a.x, b.x, -a.y * b.y), fmaf(a.x, b.y, a.y * b.x));
}
__device__ __forceinline__ float2 cfma(float2 a, float2 b, float2 acc) {
    acc.x = fmaf(a.x, b.x, fmaf(-a.y, b.y, acc.x));
    acc.y = fmaf(a.x, b.y, fmaf(a.y, b.x, acc.y));
    return acc;
}
__device__ __forceinline__ int cnot_map(int m, int c, int t) {
    int bc = 3 - c, bt = 3 - t;
    if ((m >> bc) & 1) m ^= (1 << bt);
    return m;
}

// One block, 256 threads. Builds the 81-coefficient multilinear tensor T.
__global__ void vqc_setup(const float* __restrict__ w) {
    __shared__ float2 sGate[NL * NQ][4];
    __shared__ float2 sPA[NL][16];
    __shared__ float2 sPB[NL][16];
    __shared__ float2 sUa[256], sUb[256];
    __shared__ float  sG[256];
    __shared__ float  sA1[192], sA2[144];

    const int t = threadIdx.x;

    if (t < NL * NQ) {
        float phi = w[t * 3 + 0], th = w[t * 3 + 1], om = w[t * 3 + 2];
        float st, ct; __sincosf(0.5f * th, &st, &ct);
        float a = 0.5f * (phi + om), b = 0.5f * (phi - om);
        float sa, ca, sb, cb;
        __sincosf(a, &sa, &ca);
        __sincosf(b, &sb, &cb);
        sGate[t][0] = make_float2(ca * ct, -sa * ct);
        sGate[t][1] = make_float2(-cb * st, -sb * st);
        sGate[t][2] = make_float2(cb * st, -sb * st);
        sGate[t][3] = make_float2(ca * ct, sa * ct);
    }
    {
        int col = t >> 4, m = t & 15;
        sUa[t] = make_float2(col == m ? 1.0f : 0.0f, 0.0f);
    }
    __syncthreads();

    {
        int l = t >> 5, r = t & 31;
        int which = r >> 4, idx = r & 15;
        int i = idx >> 2, j = idx & 3;
        const float2* gA = sGate[l * 4 + which * 2 + 0];
        const float2* gB = sGate[l * 4 + which * 2 + 1];
        float2 v = cmul(gA[(i >> 1) * 2 + (j >> 1)], gB[(i & 1) * 2 + (j & 1)]);
        if (which) sPB[l][idx] = v; else sPA[l][idx] = v;
    }
    __syncthreads();

    float2* cur = sUa;
    float2* nxt = sUb;
    const int col = t >> 4, m = t & 15;
    const int mh = m >> 2, ml = m & 3;
    int mp = m;
    mp = cnot_map(mp, 0, 1);
    mp = cnot_map(mp, 1, 2);
    mp = cnot_map(mp, 2, 3);
    mp = cnot_map(mp, 3, 0);
    for (int l = 0; l < NL; l++) {
        float2 acc = make_float2(0.0f, 0.0f);
#pragma unroll
        for (int nh = 0; nh < 4; nh++) {
            float2 inner = make_float2(0.0f, 0.0f);
#pragma unroll
            for (int nl = 0; nl < 4; nl++)
                inner = cfma(sPB[l][ml * 4 + nl], cur[col * 16 + nh * 4 + nl], inner);
            acc = cfma(sPA[l][mh * 4 + nh], inner, acc);
        }
        nxt[col * 16 + mp] = acc;
        __syncthreads();
        float2* tmp = cur; cur = nxt; nxt = tmp;
    }

    {
        int j = t >> 4, k = t & 15;
        float hr = 0.0f, hi = 0.0f;
#pragma unroll
        for (int mm = 0; mm < 16; mm++) {
            float zz = ((mm >> 3) & 1) ? -1.0f : 1.0f;
            float2 uj = cur[j * 16 + mm], uk = cur[k * 16 + mm];
            hr += zz * (uj.x * uk.x + uj.y * uk.y);
            hi += zz * (uj.x * uk.y - uj.y * uk.x);
        }
        int q = (__popc(j) - __popc(k)) & 3;
        float gval = (q == 0) ? hr : (q == 1) ? -hi : (q == 2) ? -hr : hi;
        int gidx = 0;
#pragma unroll
        for (int wq = 0; wq < 4; wq++) {
            int bi = 3 - wq;
            int p = ((j >> bi) & 1) * 2 + ((k >> bi) & 1);
            gidx = gidx * 4 + p;
        }
        sG[gidx] = gval;
    }
    __syncthreads();

    const float V[4][3] = {{0.5f, 0.5f, 0.0f},
                           {0.0f, 0.0f, 0.5f},
                           {0.0f, 0.0f, 0.5f},
                           {0.5f, -0.5f, 0.0f}};
    if (t < 192) {
        int d = t % 3, p2 = (t / 3) & 3, p1 = (t / 12) & 3, p0 = t / 48;
        float acc = 0.0f;
#pragma unroll
        for (int p3 = 0; p3 < 4; p3++)
            acc += sG[((p0 * 4 + p1) * 4 + p2) * 4 + p3] * V[p3][d];
        sA1[t] = acc;
    }
    __syncthreads();
    if (t < 144) {
        int d = t % 3, c = (t / 3) % 3, rest = t / 9;
        int p1 = rest & 3, p0 = rest >> 2;
        float acc = 0.0f;
#pragma unroll
        for (int p2 = 0; p2 < 4; p2++)
            acc += sA1[((p0 * 4 + p1) * 4 + p2) * 3 + d] * V[p2][c];
        sA2[t] = acc;
    }
    __syncthreads();
    if (t < 108) {
        int d = t % 3, c = (t / 3) % 3, b = (t / 9) % 3, p0 = t / 27;
        float acc = 0.0f;
#pragma unroll
        for (int p1 = 0; p1 < 4; p1++)
            acc += sA2[((p0 * 4 + p1) * 3 + c) * 3 + d] * V[p1][b];
        sA1[t] = acc;
    }
    __syncthreads();
    if (t < 81) {
        int d = t % 3, c = (t / 3) % 3, b = (t / 9) % 3, a = t / 27;
        float acc = 0.0f;
#pragma unroll
        for (int p0 = 0; p0 < 4; p0++)
            acc += sA1[((p0 * 3 + b) * 3 + c) * 3 + d] * V[p0][a];
        g_T[(a * 9 + b * 3 + c) * 4 + d] = acc;
    } else if (t < 108) {
        g_T[(t - 81) * 4 + 3] = 0.0f;
    }
}

// Contraction body: 4 samples (indices i0 + 32k), guard selects compile out
// on the fast path. Coalesced: LDG.128 lane-consecutive, STG.32 x4 coalesced.
template <bool GUARD>
__device__ __forceinline__ void run_tile(const float4* __restrict__ x,
                                         float* __restrict__ out, int n,
                                         const float4* __restrict__ sT, int i0) {
    float c0[4], s0[4], c1[4], s1[4], c2[4], s2[4], c3[4], s3[4];
#pragma unroll
    for (int k = 0; k < 4; k++) {
        int i = i0 + 32 * k;
        float4 v = (!GUARD || i < n) ? x[i] : make_float4(0.f, 0.f, 0.f, 0.f);
        __sincosf(v.x, &s0[k], &c0[k]);
        __sincosf(v.y, &s1[k], &c1[k]);
        __sincosf(v.z, &s2[k], &c2[k]);
        __sincosf(v.w, &s3[k], &c3[k]);
    }

    float E[4];
#pragma unroll
    for (int u = 0; u < 9; u++) {
        const float4 t0 = sT[u * 3 + 0];
        const float4 t1 = sT[u * 3 + 1];
        const float4 t2 = sT[u * 3 + 2];
        const int a = u / 3, b = u % 3;  // compile-time under unroll
#pragma unroll
        for (int k = 0; k < 4; k++) {
            float a0 = fmaf(t0.z, s3[k], fmaf(t0.y, c3[k], t0.x));
            float a1 = fmaf(t1.z, s3[k], fmaf(t1.y, c3[k], t1.x));
            float a2 = fmaf(t2.z, s3[k], fmaf(t2.y, c3[k], t2.x));
            float r  = fmaf(a2, s2[k], fmaf(a1, c2[k], a0));
            if (a == 0 && b == 0) {
                E[k] = r;
            } else if (a == 0) {
                E[k] = fmaf(r, (b == 1) ? c1[k] : s1[k], E[k]);
            } else if (b == 0) {
                E[k] = fmaf(r, (a == 1) ? c0[k] : s0[k], E[k]);
            } else {
                float f0v = (a == 1) ? c0[k] : s0[k];
                float f1v = (b == 1) ? c1[k] : s1[k];
                E[k] = fmaf(r * f0v, f1v, E[k]);
            }
        }
    }

#pragma unroll
    for (int k = 0; k < 4; k++) {
        int i = i0 + 32 * k;
        if (!GUARD || i < n) out[i] = E[k];
    }
}

// Main: warp owns a 128-sample tile; thread handles samples lane+32k.
// All gmem requests lane-consecutive (4 lines/warp vs 16 before). PDL overlap
// with setup; grid-dependency sync before reading g_T.
__global__ void __launch_bounds__(256, 4) vqc_main(const float4* __restrict__ x,
                                                   float* __restrict__ out, int n) {
    __shared__ __align__(16) float4 sT[28];
    const int t = threadIdx.x;
    const int warp = t >> 5, lane = t & 31;
    const int tileBase = (blockIdx.x * 8 + warp) * 128;
    const int i0 = tileBase + lane;

    // Wait for setup's g_T, stage to shared. (The launch itself overlapped
    // with setup via PDL; trig work below is post-sync — acceptable since the
    // first-wave blocks start during setup and the sync cost is absorbed once.)
    cudaGridDependencySynchronize();
    if (t < 28) sT[t] = reinterpret_cast<const float4*>(g_T)[t];
    __syncthreads();

    if (tileBase >= n) return;
    if (tileBase + 127 < n) {
        run_tile<false>(x, out, n, sT, i0);
    } else {
        run_tile<true>(x, out, n, sT, i0);
    }
}

extern "C" void kernel_launch(void* const* d_in, const int* in_sizes, int n_in,
                              void* d_out, int out_size) {
    const float* x = (const float*)d_in[0];        // (B, 4)
    const float* w = (const float*)d_in[1];        // (8, 4, 3)
    float* out = (float*)d_out;                    // (B,)
    int n = out_size;                              // B

    vqc_setup<<<1, 256>>>(w);

    int blocks = (n + 1023) / 1024;                // 1024 samples per block

    cudaLaunchConfig_t cfg = {};
    cfg.gridDim = dim3((unsigned)blocks, 1, 1);
    cfg.blockDim = dim3(256, 1, 1);
    cfg.dynamicSmemBytes = 0;
    cfg.stream = 0;
    cudaLaunchAttribute attrs[1];
    attrs[0].id = cudaLaunchAttributeProgrammaticStreamSerialization;
    attrs[0].val.programmaticStreamSerializationAllowed = 1;
    cfg.attrs = attrs;
    cfg.numAttrs = 1;
    cudaLaunchKernelEx(&cfg, vqc_main, (const float4*)x, out, n);
}

// round 10
// speedup vs baseline: 1.0962x; 1.0962x over previous
#include <cuda_runtime.h>
#include <cstdint>

#define NQ 4
#define NL 8

__device__ __align__(16) float g_T[112];   // 27 x (d0,d1,d2,pad)

__device__ __forceinline__ float2 cmul(float2 a, float2 b) {
    return make_float2(fmaf(a.x, b.x, -a.y * b.y), fmaf(a.x, b.y, a.y * b.x));
}
__device__ __forceinline__ float2 cfma(float2 a, float2 b, float2 acc) {
    acc.x = fmaf(a.x, b.x, fmaf(-a.y, b.y, acc.x));
    acc.y = fmaf(a.x, b.y, fmaf(a.y, b.x, acc.y));
    return acc;
}
__device__ __forceinline__ int cnot_map(int m, int c, int t) {
    int bc = 3 - c, bt = 3 - t;
    if ((m >> bc) & 1) m ^= (1 << bt);
    return m;
}

// One block, 256 threads. Log-depth: build 8 independent per-layer 16x16
// matrices C_l (Rot layer x CNOT ring), then 3 rounds of parallel matmuls
// (4 -> 2 -> 1) instead of 8 serial matvecs.
__global__ void vqc_setup(const float* __restrict__ w) {
    __shared__ float2 sGate[NL * NQ][4];
    __shared__ float2 sPA[NL][16];
    __shared__ float2 sPB[NL][16];
    __shared__ float2 sC[NL][256];   // per-layer matrices (row-major [i][j])
    __shared__ float2 sD[4][256];
    __shared__ float2 sE[2][256];
    __shared__ float2 sU[256];       // final U, row-major: sU[row*16+col]
    __shared__ float  sG[256];
    __shared__ float  sA1[192], sA2[144];

    const int t = threadIdx.x;

    // ---- phase 0: gate matrices ----
    if (t < NL * NQ) {
        float phi = w[t * 3 + 0], th = w[t * 3 + 1], om = w[t * 3 + 2];
        float st, ct; __sincosf(0.5f * th, &st, &ct);
        float a = 0.5f * (phi + om), b = 0.5f * (phi - om);
        float sa, ca, sb, cb;
        __sincosf(a, &sa, &ca);
        __sincosf(b, &sb, &cb);
        sGate[t][0] = make_float2(ca * ct, -sa * ct);
        sGate[t][1] = make_float2(-cb * st, -sb * st);
        sGate[t][2] = make_float2(cb * st, -sb * st);
        sGate[t][3] = make_float2(ca * ct, sa * ct);
    }
    __syncthreads();

    // ---- phase 1: pair Kronecker factors ----
    {
        int l = t >> 5, r = t & 31;
        int which = r >> 4, idx = r & 15;
        int i = idx >> 2, j = idx & 3;
        const float2* gA = sGate[l * 4 + which * 2 + 0];
        const float2* gB = sGate[l * 4 + which * 2 + 1];
        float2 v = cmul(gA[(i >> 1) * 2 + (j >> 1)], gB[(i & 1) * 2 + (j & 1)]);
        if (which) sPB[l][idx] = v; else sPA[l][idx] = v;
    }
    __syncthreads();

    // ---- phase 2: build C_l[sigma(m)][n] = PA[m>>2][n>>2]*PB[m&3][n&3] ----
    // sigma = CNOT ring applied c01,c12,c23,c30 (c01 first). 8 entries/thread.
    {
        int l = t >> 5, r = t & 31;
#pragma unroll
        for (int j = 0; j < 8; j++) {
            int idx = r + 32 * j;
            int m = idx >> 4, nn = idx & 15;
            int mp = m;
            mp = cnot_map(mp, 0, 1);
            mp = cnot_map(mp, 1, 2);
            mp = cnot_map(mp, 2, 3);
            mp = cnot_map(mp, 3, 0);
            float2 v = cmul(sPA[l][(m >> 2) * 4 + (nn >> 2)],
                            sPB[l][(m & 3) * 4 + (nn & 3)]);
            sC[l][mp * 16 + nn] = v;
        }
    }
    __syncthreads();

    // ---- phase 3: product tree. U = C7 C6 ... C0 (C0 applied first) ----
    // round 1: D_p = C_{2p+1} * C_{2p}   (4 matmuls, 4 outputs/thread)
    {
        int p = t >> 6, r = t & 63;
#pragma unroll
        for (int j = 0; j < 4; j++) {
            int idx = r + 64 * j;
            int i = idx >> 4, col = idx & 15;
            float2 acc = make_float2(0.0f, 0.0f);
#pragma unroll
            for (int k = 0; k < 16; k++)
                acc = cfma(sC[2 * p + 1][i * 16 + k], sC[2 * p][k * 16 + col], acc);
            sD[p][idx] = acc;
        }
    }
    __syncthreads();
    // round 2: E_q = D_{2q+1} * D_{2q}   (2 matmuls, 2 outputs/thread)
    {
        int qq = t >> 7, r = t & 127;
#pragma unroll
        for (int j = 0; j < 2; j++) {
            int idx = r + 128 * j;
            int i = idx >> 4, col = idx & 15;
            float2 acc = make_float2(0.0f, 0.0f);
#pragma unroll
            for (int k = 0; k < 16; k++)
                acc = cfma(sD[2 * qq + 1][i * 16 + k], sD[2 * qq][k * 16 + col], acc);
            sE[qq][idx] = acc;
        }
    }
    __syncthreads();
    // round 3: U = E1 * E0   (1 output/thread)
    {
        int i = t >> 4, col = t & 15;
        float2 acc = make_float2(0.0f, 0.0f);
#pragma unroll
        for (int k = 0; k < 16; k++)
            acc = cfma(sE[1][i * 16 + k], sE[0][k * 16 + col], acc);
        sU[t] = acc;   // row-major: element (row i, col)
    }
    __syncthreads();

    // ---- phase 4: H = U^dag Z0 U, phase-fold to real G ----
    {
        int j = t >> 4, k = t & 15;
        float hr = 0.0f, hi = 0.0f;
#pragma unroll
        for (int mm = 0; mm < 16; mm++) {
            float zz = ((mm >> 3) & 1) ? -1.0f : 1.0f;
            float2 uj = sU[mm * 16 + j], uk = sU[mm * 16 + k];
            hr += zz * (uj.x * uk.x + uj.y * uk.y);
            hi += zz * (uj.x * uk.y - uj.y * uk.x);
        }
        int q = (__popc(j) - __popc(k)) & 3;  // i^q * H, take Re
        float gval = (q == 0) ? hr : (q == 1) ? -hi : (q == 2) ? -hr : hi;
        int gidx = 0;
#pragma unroll
        for (int wq = 0; wq < 4; wq++) {
            int bi = 3 - wq;
            int p = ((j >> bi) & 1) * 2 + ((k >> bi) & 1);
            gidx = gidx * 4 + p;
        }
        sG[gidx] = gval;
    }
    __syncthreads();

    // ---- phase 5: Tucker contract pair-codes (4) with V (4x3) ----
    const float V[4][3] = {{0.5f, 0.5f, 0.0f},
                           {0.0f, 0.0f, 0.5f},
                           {0.0f, 0.0f, 0.5f},
                           {0.5f, -0.5f, 0.0f}};
    if (t < 192) {
        int d = t % 3, p2 = (t / 3) & 3, p1 = (t / 12) & 3, p0 = t / 48;
        float acc = 0.0f;
#pragma unroll
        for (int p3 = 0; p3 < 4; p3++)
            acc += sG[((p0 * 4 + p1) * 4 + p2) * 4 + p3] * V[p3][d];
        sA1[t] = acc;
    }
    __syncthreads();
    if (t < 144) {
        int d = t % 3, c = (t / 3) % 3, rest = t / 9;
        int p1 = rest & 3, p0 = rest >> 2;
        float acc = 0.0f;
#pragma unroll
        for (int p2 = 0; p2 < 4; p2++)
            acc += sA1[((p0 * 4 + p1) * 4 + p2) * 3 + d] * V[p2][c];
        sA2[t] = acc;
    }
    __syncthreads();
    if (t < 108) {
        int d = t % 3, c = (t / 3) % 3, b = (t / 9) % 3, p0 = t / 27;
        float acc = 0.0f;
#pragma unroll
        for (int p1 = 0; p1 < 4; p1++)
            acc += sA2[((p0 * 4 + p1) * 3 + c) * 3 + d] * V[p1][b];
        sA1[t] = acc;
    }
    __syncthreads();
    if (t < 81) {
        int d = t % 3, c = (t / 3) % 3, b = (t / 9) % 3, a = t / 27;
        float acc = 0.0f;
#pragma unroll
        for (int p0 = 0; p0 < 4; p0++)
            acc += sA1[((p0 * 3 + b) * 3 + c) * 3 + d] * V[p0][a];
        g_T[(a * 9 + b * 3 + c) * 4 + d] = acc;
    } else if (t < 108) {
        g_T[(t - 81) * 4 + 3] = 0.0f;
    }
}

// Contraction body: 4 samples (indices i0 + 32k). Coalesced LDG.128/STG.32.
template <bool GUARD>
__device__ __forceinline__ void run_tile(const float4* __restrict__ x,
                                         float* __restrict__ out, int n,
                                         const float4* __restrict__ sT, int i0,
                                         const float* c0, const float* s0,
                                         const float* c1, const float* s1,
                                         const float* c2, const float* s2,
                                         const float* c3, const float* s3) {
    float E[4];
#pragma unroll
    for (int u = 0; u < 9; u++) {
        const float4 t0 = sT[u * 3 + 0];
        const float4 t1 = sT[u * 3 + 1];
        const float4 t2 = sT[u * 3 + 2];
        const int a = u / 3, b = u % 3;  // compile-time under unroll
#pragma unroll
        for (int k = 0; k < 4; k++) {
            float a0 = fmaf(t0.z, s3[k], fmaf(t0.y, c3[k], t0.x));
            float a1 = fmaf(t1.z, s3[k], fmaf(t1.y, c3[k], t1.x));
            float a2 = fmaf(t2.z, s3[k], fmaf(t2.y, c3[k], t2.x));
            float r  = fmaf(a2, s2[k], fmaf(a1, c2[k], a0));
            if (a == 0 && b == 0) {
                E[k] = r;
            } else if (a == 0) {
                E[k] = fmaf(r, (b == 1) ? c1[k] : s1[k], E[k]);
            } else if (b == 0) {
                E[k] = fmaf(r, (a == 1) ? c0[k] : s0[k], E[k]);
            } else {
                float f0v = (a == 1) ? c0[k] : s0[k];
                float f1v = (b == 1) ? c1[k] : s1[k];
                E[k] = fmaf(r * f0v, f1v, E[k]);
            }
        }
    }
#pragma unroll
    for (int k = 0; k < 4; k++) {
        int i = i0 + 32 * k;
        if (!GUARD || i < n) out[i] = E[k];
    }
}

// Main: warp owns a 128-sample tile, thread handles lane+32k (coalesced).
// PDL: x loads + 16 sincos run BEFORE the grid-dependency sync, overlapping
// the setup kernel. 3 CTA/SM cap (<=85 regs) -> no spills.
__global__ void __launch_bounds__(256, 3) vqc_main(const float4* __restrict__ x,
                                                   float* __restrict__ out, int n) {
    __shared__ __align__(16) float4 sT[28];
    const int t = threadIdx.x;
    const int warp = t >> 5, lane = t & 31;
    const int tileBase = (blockIdx.x * 8 + warp) * 128;
    const int i0 = tileBase + lane;
    const bool active = (tileBase < n);
    const bool fullTile = (tileBase + 127 < n);

    // ---- T-independent prologue (overlaps setup via PDL) ----
    float c0[4], s0[4], c1[4], s1[4], c2[4], s2[4], c3[4], s3[4];
#pragma unroll
    for (int k = 0; k < 4; k++) {
        int i = i0 + 32 * k;
        float4 v = (active && (fullTile || i < n)) ? x[i]
                                                   : make_float4(0.f, 0.f, 0.f, 0.f);
        __sincosf(v.x, &s0[k], &c0[k]);
        __sincosf(v.y, &s1[k], &c1[k]);
        __sincosf(v.z, &s2[k], &c2[k]);
        __sincosf(v.w, &s3[k], &c3[k]);
    }

    // ---- wait for setup completion, stage T ----
    cudaGridDependencySynchronize();
    if (t < 28) sT[t] = reinterpret_cast<const float4*>(g_T)[t];
    __syncthreads();

    if (!active) return;
    if (fullTile) {
        run_tile<false>(x, out, n, sT, i0, c0, s0, c1, s1, c2, s2, c3, s3);
    } else {
        run_tile<true>(x, out, n, sT, i0, c0, s0, c1, s1, c2, s2, c3, s3);
    }
}

extern "C" void kernel_launch(void* const* d_in, const int* in_sizes, int n_in,
                              void* d_out, int out_size) {
    const float* x = (const float*)d_in[0];        // (B, 4)
    const float* w = (const float*)d_in[1];        // (8, 4, 3)
    float* out = (float*)d_out;                    // (B,)
    int n = out_size;                              // B

    vqc_setup<<<1, 256>>>(w);

    int blocks = (n + 1023) / 1024;                // 1024 samples per block

    cudaLaunchConfig_t cfg = {};
    cfg.gridDim = dim3((unsigned)blocks, 1, 1);
    cfg.blockDim = dim3(256, 1, 1);
    cfg.dynamicSmemBytes = 0;
    cfg.stream = 0;
    cudaLaunchAttribute attrs[1];
    attrs[0].id = cudaLaunchAttributeProgrammaticStreamSerialization;
    attrs[0].val.programmaticStreamSerializationAllowed = 1;
    cfg.attrs = attrs;
    cfg.numAttrs = 1;
    cudaLaunchKernelEx(&cfg, vqc_main, (const float4*)x, out, n);
}